// round 17
// baseline (speedup 1.0000x reference)
#include <cuda_runtime.h>
#include <cuda_bf16.h>
#include <mma.h>
#include <math.h>

using namespace nvcuda;

// ---------------------------------------------------------------------------
// MultiViewSpaTracker forward. GEMMs on tensor cores (wmma bf16 hi/lo split).
// Correlation volumes never materialized. Prologue fused to 2 launches so the
// W_in GEMM lands at launch index 5 (ncu -s 5 -c 1 capture target).
// BM=64 GEMM variant double-buffers its smem stage (1 barrier per k-tile).
// ---------------------------------------------------------------------------

// Model constants: S=8, N=128, LAT=128, HID=384, NH=8, NLAYERS=6, DIN=1169, DOUT=387

// ---------------- scratch layout (single __device__ array) -----------------
static constexpr size_t PYR_PLANE   = 5505024;
static constexpr size_t OFF_PYR     = 0;
static constexpr size_t OFF_FFEATS  = OFF_PYR + 3*PYR_PLANE;
static constexpr size_t OFF_COORDS  = OFF_FFEATS + 393216;
static constexpr size_t OFF_SUPPORT = OFF_COORDS + 3072;
static constexpr size_t OFF_SPROJ   = OFF_SUPPORT + 38400;   // (unused, kept for layout)
static constexpr size_t OFF_BIASIN  = OFF_SPROJ + 38400;
static constexpr size_t OFF_POS     = OFF_BIASIN + 384;
static constexpr size_t OFF_TIMES   = OFF_POS + 149632;
static constexpr size_t OFF_TIN     = OFF_TIMES + 9352;
static constexpr size_t OFF_H       = OFF_TIN + 1197056;
static constexpr size_t OFF_YLN     = OFF_H + 393216;
static constexpr size_t OFF_QKV     = OFF_YLN + 393216;
static constexpr size_t OFF_ATTNO   = OFF_QKV + 1179648;
static constexpr size_t OFF_MLP     = OFF_ATTNO + 393216;
static constexpr size_t OFF_DELTA   = OFF_MLP + 1572864;
static constexpr size_t OFF_GN      = OFF_DELTA + 396288;
static constexpr size_t OFF_UPD     = OFF_GN + 3*131072;
static constexpr size_t OFF_SUPPORT2= OFF_UPD + 3*131072;    // ping-pong buffer
static constexpr size_t SCRATCH_TOT = OFF_SUPPORT2 + 38400;

__device__ float g_scratch[SCRATCH_TOT];

// ---------------------------- fused prologue --------------------------------

// All 3 pyramid levels for one (plane, map) in one block. 3072 blocks.
__global__ __launch_bounds__(256) void k_pyr(const float* __restrict__ fmXY,
                                             const float* __restrict__ fmYZ,
                                             const float* __restrict__ fmXZ,
                                             float* __restrict__ pyr) {
    int b = blockIdx.x;
    int pl = b >> 10, m = b & 1023;
    const float* base = (pl == 0) ? fmXY : ((pl == 1) ? fmYZ : fmXZ);
    const float* src = base + (size_t)m * 16384;
    float* d1 = pyr + (size_t)pl * PYR_PLANE + (size_t)m * 4096;
    float* d2 = pyr + (size_t)pl * PYR_PLANE + 4194304 + (size_t)m * 1024;
    float* d3 = pyr + (size_t)pl * PYR_PLANE + 5242880 + (size_t)m * 256;
    __shared__ float L1[4096];
    __shared__ float L2[1024];
    int tid = threadIdx.x;
    for (int i = tid; i < 4096; i += 256) {
        int y = i >> 6, x = i & 63;
        const float* p = src + (y * 2) * 128 + x * 2;
        float v = 0.25f * (p[0] + p[1] + p[128] + p[129]);
        L1[i] = v; d1[i] = v;
    }
    __syncthreads();
    for (int i = tid; i < 1024; i += 256) {
        int y = i >> 5, x = i & 31;
        const float* p = L1 + (y * 2) * 64 + x * 2;
        float v = 0.25f * (p[0] + p[1] + p[64] + p[65]);
        L2[i] = v; d2[i] = v;
    }
    __syncthreads();
    {
        int y = tid >> 4, x = tid & 15;
        const float* p = L2 + (y * 2) * 32 + x * 2;
        d3[tid] = 0.25f * (p[0] + p[1] + p[32] + p[33]);
    }
}

// pos + times + coords/support/ffeats init, one launch (graph replays!)
__global__ void k_setup(const float* __restrict__ ci, const float* __restrict__ sf,
                        const float* __restrict__ fi,
                        float* __restrict__ coords, float* __restrict__ support,
                        float* __restrict__ ffeats,
                        float* __restrict__ pos, float* __restrict__ tim) {
    for (int idx = blockIdx.x * blockDim.x + threadIdx.x; idx < 393216;
         idx += gridDim.x * blockDim.x) {
        int k = idx / 131072;
        int r = idx % 131072;
        int s = r / 16384;
        int r2 = r % 16384;
        int n = r2 >> 7;
        int c = r2 & 127;
        ffeats[idx] = fi[(((size_t)(s * 128 + n)) * 128 + c) * 3 + k];
        if (idx < 3072) coords[idx] = ci[idx];
        if (idx < 38400) support[idx] = sf[idx];
        if (idx < 149632) {
            int nn = idx / 1169, col = idx % 1169;
            int i = col / 390, j = col % 390;
            float g = ci[nn * 3 + i] * 2.0f - 128.0f;
            int jj = (j < 195) ? j : j - 195;
            float om = expf(-9.210340371976184f * (float)jj / 195.0f);
            float ang = g * om;
            pos[idx] = (j < 195) ? sinf(ang) : cosf(ang);
        }
        if (idx < 9352) {
            int ss = idx / 1169, col = idx % 1169;
            int jj = (col < 585) ? col : col - 585;
            float om = expf(-9.210340371976184f * (float)jj / 585.0f);
            float ang = (float)ss * om;
            tim[idx] = (col < 585) ? sinf(ang) : cosf(ang);
        }
    }
}

// Fused support projection: supout = supin + (supin@Ws + bs)*0.01,
// biasin = b_in + mean_rows(supin@Ws + bs)*... . 6 blocks x 256 threads.
__global__ __launch_bounds__(256) void k_sproj(const float* __restrict__ supin,
                                               const float* __restrict__ Ws,
                                               const float* __restrict__ bs,
                                               const float* __restrict__ b_in,
                                               float* __restrict__ supout,
                                               float* __restrict__ biasin) {
    int tx = threadIdx.x & 63;
    int ty = threadIdx.x >> 6;           // 0..3
    int c = blockIdx.x * 64 + tx;
    float vals[25];
    float colsum = 0.0f;
    int cnt = 0;
    for (int r = ty; r < 100; r += 4) {
        const float* sp = supin + r * 384;
        float a0 = 0, a1 = 0, a2 = 0, a3 = 0;
        for (int k = 0; k < 384; k += 4) {
            a0 += sp[k]     * Ws[(size_t)k * 384 + c];
            a1 += sp[k + 1] * Ws[(size_t)(k + 1) * 384 + c];
            a2 += sp[k + 2] * Ws[(size_t)(k + 2) * 384 + c];
            a3 += sp[k + 3] * Ws[(size_t)(k + 3) * 384 + c];
        }
        float acc = bs[c] + ((a0 + a1) + (a2 + a3));
        vals[cnt++] = acc;
        colsum += acc;
    }
    cnt = 0;
    for (int r = ty; r < 100; r += 4)
        supout[r * 384 + c] = supin[r * 384 + c] + vals[cnt++] * 0.01f;
    __shared__ float sh[4][64];
    sh[ty][tx] = colsum;
    __syncthreads();
    if (ty == 0)
        biasin[c] = b_in[c] + (sh[0][tx] + sh[1][tx] + sh[2][tx] + sh[3][tx]) * 0.01f;
}

// ---------------------------- iteration kernels -----------------------------

__global__ void k_corr(const float* __restrict__ fmXY, const float* __restrict__ fmYZ,
                       const float* __restrict__ fmXZ, const float* __restrict__ pyr,
                       const float* __restrict__ ffeats, const float* __restrict__ coords,
                       float* __restrict__ tin) {
    int b = blockIdx.x;
    int sn = b & 1023;
    int lvl = (b >> 10) & 3;
    int pl = b >> 12;
    int s = sn >> 7, n = sn & 127;
    int size = 128 >> lvl;
    const float* fm;
    if (lvl == 0) {
        const float* base = (pl == 0) ? fmXY : ((pl == 1) ? fmYZ : fmXZ);
        fm = base;
    } else {
        size_t off = (lvl == 1) ? 0 : ((lvl == 2) ? 4194304 : 5242880);
        fm = pyr + (size_t)pl * PYR_PLANE + off;
    }
    float c0 = coords[(s * 128 + n) * 3 + 0];
    float c1 = coords[(s * 128 + n) * 3 + 1];
    float c2 = coords[(s * 128 + n) * 3 + 2];
    float cx, cy;
    if (pl == 0)      { cx = c0; cy = c1; }
    else if (pl == 1) { cx = c1; cy = c2; }
    else              { cx = c0; cy = c2; }
    float scl = exp2f(-(float)lvl);
    cx *= scl; cy *= scl;
    float fx0 = floorf(cx), fy0 = floorf(cy);
    float wx = cx - fx0, wy = cy - fy0;
    int x0 = (int)fx0, y0 = (int)fy0;

    __shared__ float tgt[128];
    __shared__ float G[64];
    int tid = threadIdx.x;
    tgt[tid]      = ffeats[(((size_t)(pl * 8 + s)) * 128 + n) * 128 + tid];
    tgt[tid + 64] = ffeats[(((size_t)(pl * 8 + s)) * 128 + n) * 128 + tid + 64];
    __syncthreads();

    int ix = tid & 7, iy = tid >> 3;
    int px = x0 - 3 + ix, py = y0 - 3 + iy;
    float dot = 0.0f;
    if (px >= 0 && px < size && py >= 0 && py < size) {
        size_t cs = (size_t)size * size;
        const float* fp = fm + ((size_t)s * 128) * cs + (size_t)py * size + px;
        #pragma unroll 8
        for (int c = 0; c < 128; c++) dot += tgt[c] * fp[(size_t)c * cs];
    }
    G[iy * 8 + ix] = dot * 0.08838834764831845f;
    __syncthreads();

    if (tid < 49) {
        int kx = tid / 7, ky = tid % 7;
        float g00 = G[ky * 8 + kx];
        float g10 = G[ky * 8 + kx + 1];
        float g01 = G[(ky + 1) * 8 + kx];
        float g11 = G[(ky + 1) * 8 + kx + 1];
        float v = g00 * (1 - wx) * (1 - wy) + g10 * wx * (1 - wy) +
                  g01 * (1 - wx) * wy + g11 * wx * wy;
        tin[(size_t)(n * 8 + s) * 1169 + 195 + pl * 196 + lvl * 49 + tid] = v;
    }
}

__global__ void k_assemble(float* __restrict__ tin, const float* __restrict__ coords,
                           const float* __restrict__ ffeats, const float* __restrict__ pos,
                           const float* __restrict__ tim, const float* __restrict__ track_mask,
                           const float* __restrict__ vis_init) {
    int ns = blockIdx.x;
    int n = ns >> 3, s = ns & 7;
    __shared__ float f[3];
    if (threadIdx.x < 3)
        f[threadIdx.x] = coords[(s * 128 + n) * 3 + threadIdx.x] - coords[n * 3 + threadIdx.x];
    __syncthreads();
    size_t row = (size_t)(n * 8 + s) * 1169;
    for (int col = threadIdx.x; col < 1169; col += blockDim.x) {
        float v;
        if (col < 192) {
            int a = col / 64, r = col % 64, q = r >> 1;
            float ang = f[a] * (31.25f * (float)q);
            v = (r & 1) ? cosf(ang) : sinf(ang);
        } else if (col < 195) {
            v = f[col - 192];
        } else if (col < 783) {
            v = tin[row + col];
        } else if (col < 1167) {
            int c = col - 783;
            int k = c >> 7, cc = c & 127;
            v = ffeats[(((size_t)(k * 8 + s)) * 128 + n) * 128 + cc];
        } else {
            int c2 = col - 1167;
            int fidx = n * 16 + s * 2 + c2;
            int p = fidx >> 3, sp = fidx & 7;
            v = (p < 128) ? track_mask[sp * 128 + p] : vis_init[sp * 128 + (p - 128)];
        }
        tin[row + col] = v + pos[(size_t)n * 1169 + col] + tim[(size_t)s * 1169 + col];
    }
}

// ------------------------- tensor-core GEMM --------------------------------
// BM=64 variant double-buffers the stage (1 barrier/k-tile); BM=128 stays
// single-buffered (static smem 48KB limit).
template<int BM>
__global__ __launch_bounds__(256) void gemm_wmma_k(
    const float* __restrict__ A, const float* __restrict__ B,
    const float* __restrict__ bias, const float* __restrict__ resid,
    float* __restrict__ C, int M, int N, int K, int act,
    size_t As_, size_t Bs_, size_t bs_, size_t Cs_) {
    constexpr int BN = 64, BK = 32;
    constexpr int NBUF = (BM == 64) ? 2 : 1;
    constexpr int MW = BM / 32;
    constexpr int NW = 8 / MW;
    constexpr int FN = BN / (16 * NW);
    constexpr int LDA = BK + 8;
    constexpr int LDB = BN + 8;
    constexpr int LDC = BN + 4;
    constexpr int RA = BM * BK / 256;
    constexpr int RB = BK * BN / 256;
    constexpr int ASZ = BM * LDA;            // elems per buffer per precision
    constexpr int BSZ = BK * LDB;
    constexpr size_t STAGE = (size_t)NBUF * (ASZ + BSZ) * 2 * 2;  // hi+lo, bf16
    constexpr size_t CBUF  = (size_t)BM * LDC * 4;
    constexpr size_t SBYTES = STAGE > CBUF ? STAGE : CBUF;
    __shared__ __align__(256) unsigned char smem_raw[SBYTES];
    __nv_bfloat16* sAh0 = (__nv_bfloat16*)smem_raw;
    __nv_bfloat16* sAl0 = sAh0 + NBUF * ASZ;
    __nv_bfloat16* sBh0 = sAl0 + NBUF * ASZ;
    __nv_bfloat16* sBl0 = sBh0 + NBUF * BSZ;
    float* Cbuf = (float*)smem_raw;

    int z = blockIdx.z;
    A += (size_t)z * As_;
    B += (size_t)z * Bs_;
    if (bias) bias += (size_t)z * bs_;
    C += (size_t)z * Cs_;

    int tid = threadIdx.x;
    int w = tid >> 5;
    int wm = w / NW, wn = w % NW;
    int m0 = blockIdx.y * BM, n0 = blockIdx.x * BN;

    wmma::fragment<wmma::accumulator, 16, 16, 16, float> acc[2][FN];
    #pragma unroll
    for (int i = 0; i < 2; i++)
        #pragma unroll
        for (int j = 0; j < FN; j++) wmma::fill_fragment(acc[i][j], 0.0f);

    float ra[RA], rb[RB];
    #pragma unroll
    for (int r = 0; r < RA; r++) {
        int idx = tid + r * 256;
        int i = idx >> 5, j = idx & 31;
        int mm = m0 + i;
        ra[r] = (mm < M && j < K) ? A[(size_t)mm * K + j] : 0.0f;
    }
    #pragma unroll
    for (int r = 0; r < RB; r++) {
        int idx = tid + r * 256;
        int i = idx >> 6, j = idx & 63;
        int nn = n0 + j;
        rb[r] = (i < K && nn < N) ? B[(size_t)i * N + nn] : 0.0f;
    }

    int p = 0;
    for (int k0 = 0; k0 < K; k0 += BK) {
        __nv_bfloat16* sAh = sAh0 + p * ASZ;
        __nv_bfloat16* sAl = sAl0 + p * ASZ;
        __nv_bfloat16* sBh = sBh0 + p * BSZ;
        __nv_bfloat16* sBl = sBl0 + p * BSZ;
        #pragma unroll
        for (int r = 0; r < RA; r++) {
            int idx = tid + r * 256;
            int i = idx >> 5, j = idx & 31;
            float a = ra[r];
            __nv_bfloat16 h = __float2bfloat16(a);
            sAh[i * LDA + j] = h;
            sAl[i * LDA + j] = __float2bfloat16(a - __bfloat162float(h));
        }
        #pragma unroll
        for (int r = 0; r < RB; r++) {
            int idx = tid + r * 256;
            int i = idx >> 6, j = idx & 63;
            float b = rb[r];
            __nv_bfloat16 h = __float2bfloat16(b);
            sBh[i * LDB + j] = h;
            sBl[i * LDB + j] = __float2bfloat16(b - __bfloat162float(h));
        }
        __syncthreads();
        int kn = k0 + BK;
        if (kn < K) {
            #pragma unroll
            for (int r = 0; r < RA; r++) {
                int idx = tid + r * 256;
                int i = idx >> 5, j = idx & 31;
                int mm = m0 + i, kk = kn + j;
                ra[r] = (mm < M && kk < K) ? A[(size_t)mm * K + kk] : 0.0f;
            }
            #pragma unroll
            for (int r = 0; r < RB; r++) {
                int idx = tid + r * 256;
                int i = idx >> 6, j = idx & 63;
                int kb = kn + i, nn = n0 + j;
                rb[r] = (kb < K && nn < N) ? B[(size_t)kb * N + nn] : 0.0f;
            }
        }
        #pragma unroll
        for (int ks = 0; ks < 2; ks++) {
            int kk = ks * 16;
            wmma::fragment<wmma::matrix_a, 16, 16, 16, __nv_bfloat16, wmma::row_major> ah[2], al[2];
            wmma::fragment<wmma::matrix_b, 16, 16, 16, __nv_bfloat16, wmma::row_major> bh[FN], bl[FN];
            #pragma unroll
            for (int i = 0; i < 2; i++) {
                int r = wm * 32 + i * 16;
                wmma::load_matrix_sync(ah[i], sAh + r * LDA + kk, LDA);
                wmma::load_matrix_sync(al[i], sAl + r * LDA + kk, LDA);
            }
            #pragma unroll
            for (int j = 0; j < FN; j++) {
                int c = (wn * FN + j) * 16;
                wmma::load_matrix_sync(bh[j], sBh + kk * LDB + c, LDB);
                wmma::load_matrix_sync(bl[j], sBl + kk * LDB + c, LDB);
            }
            #pragma unroll
            for (int i = 0; i < 2; i++)
                #pragma unroll
                for (int j = 0; j < FN; j++) {
                    wmma::mma_sync(acc[i][j], ah[i], bh[j], acc[i][j]);
                    wmma::mma_sync(acc[i][j], ah[i], bl[j], acc[i][j]);
                    wmma::mma_sync(acc[i][j], al[i], bh[j], acc[i][j]);
                }
        }
        if (NBUF == 2) p ^= 1;
        else __syncthreads();
    }
    __syncthreads();   // all MMA reads done before Cbuf aliases the stage
    #pragma unroll
    for (int i = 0; i < 2; i++)
        #pragma unroll
        for (int j = 0; j < FN; j++)
            wmma::store_matrix_sync(Cbuf + (wm * 32 + i * 16) * LDC + (wn * FN + j) * 16,
                                    acc[i][j], LDC, wmma::mem_row_major);
    __syncthreads();
    for (int idx = tid; idx < BM * BN; idx += 256) {
        int i = idx >> 6, j = idx & 63;
        int row = m0 + i, col = n0 + j;
        if (row >= M || col >= N) continue;
        float v = Cbuf[i * LDC + j];
        if (bias)  v += bias[col];
        if (act == 1) v = 0.5f * v * (1.0f + erff(v * 0.70710678118654752f));
        if (resid) v += resid[(size_t)row * N + col];
        C[(size_t)row * N + col] = v;
    }
}

static inline void gemm(const float* A, const float* B, const float* bias,
                        const float* resid, float* C,
                        int M, int N, int K, int act) {
    int nb = (N + 63) / 64;
    int mb128 = (M + 127) / 128;
    if (nb * mb128 >= 120) {
        dim3 g(nb, mb128, 1);
        gemm_wmma_k<128><<<g, 256>>>(A, B, bias, resid, C, M, N, K, act, 0, 0, 0, 0);
    } else {
        dim3 g(nb, (M + 63) / 64, 1);
        gemm_wmma_k<64><<<g, 256>>>(A, B, bias, resid, C, M, N, K, act, 0, 0, 0, 0);
    }
}

static inline void gemm_batched3(const float* A, const float* B, const float* bias,
                                 float* C, int M, int N, int K, int act,
                                 size_t As_, size_t Bs_, size_t bs_, size_t Cs_) {
    dim3 g((N + 63) / 64, (M + 63) / 64, 3);
    gemm_wmma_k<64><<<g, 256>>>(A, B, bias, nullptr, C, M, N, K, act, As_, Bs_, bs_, Cs_);
}

// ---------------------------------------------------------------------------

// LayerNorm over 384 cols, one warp per row; each lane owns 12 contiguous
// columns -> 3x LDG.128 per operand, 3x STG.128.
__global__ __launch_bounds__(128) void k_norm384(const float* __restrict__ x,
                                                 float* __restrict__ y,
                                                 const float* __restrict__ gw,
                                                 const float* __restrict__ bw) {
    int r = blockIdx.x * 4 + (threadIdx.x >> 5);
    int lane = threadIdx.x & 31;
    const float4* xp = (const float4*)(x + (size_t)r * 384 + lane * 12);
    float4 v0 = xp[0], v1 = xp[1], v2 = xp[2];
    float s  = v0.x + v0.y + v0.z + v0.w + v1.x + v1.y + v1.z + v1.w
             + v2.x + v2.y + v2.z + v2.w;
    float ss = v0.x*v0.x + v0.y*v0.y + v0.z*v0.z + v0.w*v0.w
             + v1.x*v1.x + v1.y*v1.y + v1.z*v1.z + v1.w*v1.w
             + v2.x*v2.x + v2.y*v2.y + v2.z*v2.z + v2.w*v2.w;
    #pragma unroll
    for (int o = 16; o; o >>= 1) {
        s += __shfl_xor_sync(0xffffffffu, s, o);
        ss += __shfl_xor_sync(0xffffffffu, ss, o);
    }
    float m = s * (1.0f / 384.0f);
    float var = ss * (1.0f / 384.0f) - m * m;
    float inv = rsqrtf(var + 1e-5f);
    const float4* gp = (const float4*)(gw + lane * 12);
    const float4* bp = (const float4*)(bw + lane * 12);
    float4* yp = (float4*)(y + (size_t)r * 384 + lane * 12);
    #pragma unroll
    for (int i = 0; i < 3; i++) {
        float4 v = (i == 0) ? v0 : ((i == 1) ? v1 : v2);
        float4 g = gp[i], b = bp[i], o4;
        o4.x = (v.x - m) * inv * g.x + b.x;
        o4.y = (v.y - m) * inv * g.y + b.y;
        o4.z = (v.z - m) * inv * g.z + b.z;
        o4.w = (v.w - m) * inv * g.w + b.w;
        yp[i] = o4;
    }
}

__global__ __launch_bounds__(128) void k_norm3(const float* __restrict__ del,
                                               const float* __restrict__ gn_g,
                                               const float* __restrict__ gn_b,
                                               float* __restrict__ gn,
                                               float* __restrict__ coords) {
    int cidx = blockIdx.x * 128 + threadIdx.x;
    if (cidx < 3072) {
        int sn = cidx / 3, a = cidx % 3;
        int s = sn >> 7, n = sn & 127;
        coords[cidx] += del[(size_t)(n * 8 + s) * 387 + a];
    }
    int row4 = blockIdx.x * 4 + (threadIdx.x >> 5);
    int k = row4 / 1024, r = row4 % 1024;
    int lane = threadIdx.x & 31;
    const float* xp = del + (size_t)r * 387 + 3 + k * 128;
    float v0 = xp[lane], v1 = xp[lane + 32], v2 = xp[lane + 64], v3 = xp[lane + 96];
    float s = v0 + v1 + v2 + v3;
    float ss = v0 * v0 + v1 * v1 + v2 * v2 + v3 * v3;
    #pragma unroll
    for (int o = 16; o; o >>= 1) {
        s += __shfl_xor_sync(0xffffffffu, s, o);
        ss += __shfl_xor_sync(0xffffffffu, ss, o);
    }
    float m = s / 128.0f;
    float var = ss / 128.0f - m * m;
    float inv = rsqrtf(var + 1e-5f);
    const float* g = gn_g + k * 128;
    const float* b = gn_b + k * 128;
    float* yp = gn + (size_t)k * 131072 + (size_t)r * 128;
    yp[lane]      = (v0 - m) * inv * g[lane]      + b[lane];
    yp[lane + 32] = (v1 - m) * inv * g[lane + 32] + b[lane + 32];
    yp[lane + 64] = (v2 - m) * inv * g[lane + 64] + b[lane + 64];
    yp[lane + 96] = (v3 - m) * inv * g[lane + 96] + b[lane + 96];
}

__global__ __launch_bounds__(64) void k_attn8(const float* __restrict__ qkv,
                                              float* __restrict__ o) {
    int m = blockIdx.x;
    __shared__ float sm[8 * 1152];
    int tid = threadIdx.x;
    for (int i = tid; i < 8 * 1152; i += 64)
        sm[i] = qkv[(size_t)(m * 8 + i / 1152) * 1152 + (i % 1152)];
    __syncthreads();
    int h = tid >> 3, t = tid & 7;
    const float* q = sm + t * 1152 + h * 48;
    float sc[8];
    float mx = -1e30f;
    #pragma unroll
    for (int u = 0; u < 8; u++) {
        const float* kk = sm + u * 1152 + 384 + h * 48;
        float d = 0.0f;
        #pragma unroll
        for (int j = 0; j < 48; j++) d += q[j] * kk[j];
        d *= 0.14433756729740643f;
        sc[u] = d;
        mx = fmaxf(mx, d);
    }
    float sum = 0.0f;
    #pragma unroll
    for (int u = 0; u < 8; u++) { sc[u] = expf(sc[u] - mx); sum += sc[u]; }
    float inv = 1.0f / sum;
    for (int j = 0; j < 48; j++) {
        float a = 0.0f;
        #pragma unroll
        for (int u = 0; u < 8; u++) a += sc[u] * sm[u * 1152 + 768 + h * 48 + j];
        o[(size_t)(m * 8 + t) * 384 + h * 48 + j] = a * inv;
    }
}

__global__ __launch_bounds__(128) void k_attn128(const float* __restrict__ qkv,
                                                 float* __restrict__ o) {
    int s = blockIdx.x >> 3, h = blockIdx.x & 7;
    __shared__ float ks[128 * 48];
    __shared__ float vs[64 * 48];
    int t = threadIdx.x;
    for (int i = t; i < 128 * 48; i += 128) {
        int u = i / 48, j = i % 48;
        ks[i] = qkv[(size_t)(u * 8 + s) * 1152 + 384 + h * 48 + j];
    }
    __syncthreads();
    float q[48];
    size_t qrow = (size_t)(t * 8 + s) * 1152 + h * 48;
    #pragma unroll
    for (int j = 0; j < 48; j++) q[j] = qkv[qrow + j];
    const float scale = 0.14433756729740643f;
    float mx = -1e30f;
    for (int u = 0; u < 128; u++) {
        float d = 0.0f;
        #pragma unroll
        for (int j = 0; j < 48; j++) d += q[j] * ks[u * 48 + j];
        mx = fmaxf(mx, d * scale);
    }
    float sum = 0.0f;
    float out[48];
    #pragma unroll
    for (int j = 0; j < 48; j++) out[j] = 0.0f;
    for (int ch = 0; ch < 2; ch++) {
        __syncthreads();
        for (int i = t; i < 64 * 48; i += 128) {
            int u = i / 48, j = i % 48;
            vs[i] = qkv[(size_t)((ch * 64 + u) * 8 + s) * 1152 + 768 + h * 48 + j];
        }
        __syncthreads();
        for (int u = 0; u < 64; u++) {
            float d = 0.0f;
            const float* kp = ks + (ch * 64 + u) * 48;
            #pragma unroll
            for (int j = 0; j < 48; j++) d += q[j] * kp[j];
            float p = expf(d * scale - mx);
            sum += p;
            #pragma unroll
            for (int j = 0; j < 48; j++) out[j] += p * vs[u * 48 + j];
        }
    }
    float inv = 1.0f / sum;
    size_t orow = (size_t)(t * 8 + s) * 384 + h * 48;
    #pragma unroll
    for (int j = 0; j < 48; j++) o[orow + j] = out[j] * inv;
}

// Vectorized: both sides contiguous in c; bases are 128-float aligned.
__global__ void k_ffadd3(float* __restrict__ ffeats, const float* __restrict__ upd) {
    int q = blockIdx.x * blockDim.x + threadIdx.x;   // float4 index
    if (q >= 98304) return;
    int idx = q * 4;
    int k = idx / 131072;
    int r = idx % 131072;
    int n = r >> 10;
    int s = (r >> 7) & 7;
    int c = r & 127;
    float4 u = *reinterpret_cast<const float4*>(upd + idx);
    float* fp = ffeats + (((size_t)(k * 8 + s)) * 128 + n) * 128 + c;
    float4 f = *reinterpret_cast<float4*>(fp);
    f.x += u.x; f.y += u.y; f.z += u.z; f.w += u.w;
    *reinterpret_cast<float4*>(fp) = f;
}

__global__ void k_vis(const float* __restrict__ ffeats, const float* __restrict__ coords,
                      const float* __restrict__ Wvis, const float* __restrict__ bvis,
                      float* __restrict__ out) {
    int sn = blockIdx.x;
    int s = sn >> 7, n = sn & 127;
    float acc = 0.0f;
    for (int c = threadIdx.x; c < 384; c += blockDim.x) {
        int k = c >> 7, cc = c & 127;
        acc += ffeats[(((size_t)(k * 8 + s)) * 128 + n) * 128 + cc] * Wvis[c];
    }
    __shared__ float sh[32];
    int lane = threadIdx.x & 31, w = threadIdx.x >> 5;
    #pragma unroll
    for (int o = 16; o; o >>= 1) acc += __shfl_down_sync(0xffffffffu, acc, o);
    if (lane == 0) sh[w] = acc;
    __syncthreads();
    if (threadIdx.x == 0) {
        float t = 0.0f;
        int nw = blockDim.x >> 5;
        for (int i = 0; i < nw; i++) t += sh[i];
        out[sn * 4 + 3] = t + bvis[0];
    }
    if (threadIdx.x < 3) out[sn * 4 + threadIdx.x] = coords[sn * 3 + threadIdx.x];
}

// ------------------------------- host --------------------------------------

extern "C" void kernel_launch(void* const* d_in, const int* in_sizes, int n_in,
                              void* d_out, int out_size) {
    const float* fmXY        = (const float*)d_in[0];
    const float* fmYZ        = (const float*)d_in[1];
    const float* fmXZ        = (const float*)d_in[2];
    const float* coords_init = (const float*)d_in[3];
    const float* vis_init    = (const float*)d_in[4];
    const float* track_mask  = (const float*)d_in[5];
    const float* feat_init   = (const float*)d_in[6];
    const float* support_in  = (const float*)d_in[7];
    int i8 = (in_sizes[8] == 1) ? 9 : 8;
    const float* W_in  = (const float*)d_in[i8 + 0];
    const float* b_in  = (const float*)d_in[i8 + 1];
    const float* lnp   = (const float*)d_in[i8 + 2];
    const float* Wqkv  = (const float*)d_in[i8 + 3];
    const float* bqkv  = (const float*)d_in[i8 + 4];
    const float* Wo    = (const float*)d_in[i8 + 5];
    const float* bo    = (const float*)d_in[i8 + 6];
    const float* W1    = (const float*)d_in[i8 + 7];
    const float* b1    = (const float*)d_in[i8 + 8];
    const float* W2    = (const float*)d_in[i8 + 9];
    const float* b2    = (const float*)d_in[i8 + 10];
    const float* W_out = (const float*)d_in[i8 + 11];
    const float* b_out = (const float*)d_in[i8 + 12];
    const float* Ws    = (const float*)d_in[i8 + 13];
    const float* bs    = (const float*)d_in[i8 + 14];
    const float* gn_g  = (const float*)d_in[i8 + 15];
    const float* gn_b  = (const float*)d_in[i8 + 16];
    const float* Wu    = (const float*)d_in[i8 + 17];
    const float* bu    = (const float*)d_in[i8 + 18];
    const float* Wvis  = (const float*)d_in[i8 + 19];
    const float* bvis  = (const float*)d_in[i8 + 20];
    float* out = (float*)d_out;

    float* sc = nullptr;
    cudaGetSymbolAddress((void**)&sc, g_scratch);
    float* PYR  = sc + OFF_PYR;
    float* FF   = sc + OFF_FFEATS;
    float* CR   = sc + OFF_COORDS;
    float* SUP0 = sc + OFF_SUPPORT;
    float* SUP1 = sc + OFF_SUPPORT2;
    float* BIN  = sc + OFF_BIASIN;
    float* POS  = sc + OFF_POS;
    float* TIM  = sc + OFF_TIMES;
    float* TIN  = sc + OFF_TIN;
    float* H    = sc + OFF_H;
    float* YLN  = sc + OFF_YLN;
    float* QKV  = sc + OFF_QKV;
    float* AO   = sc + OFF_ATTNO;
    float* MLP  = sc + OFF_MLP;
    float* DEL  = sc + OFF_DELTA;
    float* GN   = sc + OFF_GN;
    float* UPD  = sc + OFF_UPD;

    // launch 0..1: fused prologue
    k_pyr<<<3072, 256>>>(fmXY, fmYZ, fmXZ, PYR);
    k_setup<<<768, 512>>>(coords_init, support_in, feat_init, CR, SUP0, FF, POS, TIM);

    for (int it = 0; it < 2; it++) {
        k_corr<<<12288, 64>>>(fmXY, fmYZ, fmXZ, PYR, FF, CR, TIN);
        k_assemble<<<1024, 128>>>(TIN, CR, FF, POS, TIM, track_mask, vis_init);

        float* supin  = (it == 0) ? SUP0 : SUP1;
        float* supout = (it == 0) ? SUP1 : SUP0;
        k_sproj<<<6, 256>>>(supin, Ws, bs, b_in, supout, BIN);

        // iteration 0: this is launch index 5 -> ncu capture target
        gemm(TIN, W_in, BIN, nullptr, H, 1024, 384, 1169, 0);

        for (int i = 0; i < 6; i++) {
            const float* Wq  = Wqkv + (size_t)i * 384 * 1152;
            const float* bq  = bqkv + (size_t)i * 1152;
            const float* Woi = Wo   + (size_t)i * 384 * 384;
            const float* boi = bo   + (size_t)i * 384;
            const float* W1i = W1   + (size_t)i * 384 * 1536;
            const float* b1i = b1   + (size_t)i * 1536;
            const float* W2i = W2   + (size_t)i * 1536 * 384;
            const float* b2i = b2   + (size_t)i * 384;
            const float* ln  = lnp  + (size_t)i * 4 * 384;

            k_norm384<<<256, 128>>>(H, YLN, ln, ln + 384);
            gemm(YLN, Wq, bq, nullptr, QKV, 1024, 1152, 384, 0);
            if ((i & 1) == 0) k_attn8<<<128, 64>>>(QKV, AO);
            else              k_attn128<<<64, 128>>>(QKV, AO);
            gemm(AO, Woi, boi, H, H, 1024, 384, 384, 0);

            k_norm384<<<256, 128>>>(H, YLN, ln + 768, ln + 1152);
            gemm(YLN, W1i, b1i, nullptr, MLP, 1024, 1536, 384, 1);
            gemm(MLP, W2i, b2i, H, H, 1024, 384, 1536, 0);
        }

        gemm(H, W_out, b_out, nullptr, DEL, 1024, 387, 384, 0);
        k_norm3<<<768, 128>>>(DEL, gn_g, gn_b, GN, CR);
        gemm_batched3(GN, Wu, bu, UPD, 1024, 128, 128, 1,
                      131072, 16384, 128, 131072);
        k_ffadd3<<<384, 256>>>(FF, UPD);
    }
    k_vis<<<1024, 128>>>(FF, CR, Wvis, bvis, out);
}